// round 8
// baseline (speedup 1.0000x reference)
#include <cuda_runtime.h>
#include <cuda_bf16.h>

// ---------------- problem constants ----------------
#define N_WORDS   4096
#define WORD_LEN  16
#define GLOVE_DIM 300
#define CHAR_EMB  50
#define CHAR_HID  128
#define G4        512           // 4*CHAR_HID
#define HIDDEN    512
#define FEAT      428           // GLOVE_DIM + CHAR_HID
#define WPB       32            // words per block
#define NBLK      (N_WORDS / WPB)   // 128
#define HSTRIDE   34            // padded h row stride (floats)

typedef unsigned long long ull;

// ---------------- device scratch (static; no allocations allowed) ----------------
__device__ ull   g_Wih2[CHAR_EMB * G4];     // [k][gate][n]  duplicated {w,w}
__device__ ull   g_Whh2[CHAR_HID * G4];     // [k][gate][n]  duplicated {w,w}
__device__ float g_bsum[G4];                // b_ih + b_hh
__device__ float g_Gpart[NBLK * GLOVE_DIM];
__device__ float g_Hpart[NBLK * CHAR_HID];
__device__ float g_avg[FEAT];
__device__ float g_hid[HIDDEN];

// ---------------- packed f32x2 helpers ----------------
static __device__ __forceinline__ ull pack2(float lo, float hi) {
    ull r;
    asm("mov.b64 %0, {%1, %2};" : "=l"(r) : "f"(lo), "f"(hi));
    return r;
}
static __device__ __forceinline__ void unpack2(ull v, float &lo, float &hi) {
    asm("mov.b64 {%0, %1}, %2;" : "=f"(lo), "=f"(hi) : "l"(v));
}
static __device__ __forceinline__ void ffma2(ull &d, ull a, ull b) {
    // d = a * b + d   (two independent fp32 FMAs per instruction)
    asm("fma.rn.f32x2 %0, %1, %2, %0;" : "+l"(d) : "l"(a), "l"(b));
}

static __device__ __forceinline__ float sigmf(float x) {
    return __fdividef(1.0f, 1.0f + __expf(-x));
}
static __device__ __forceinline__ float tanhf_(float x) {
    float e = __expf(2.0f * x);
    return __fdividef(e - 1.0f, e + 1.0f);
}

// ---------------- prep: transpose + duplicate weights, fold bias ----------------
__global__ void prep_kernel(const float* __restrict__ W_ih,
                            const float* __restrict__ W_hh,
                            const float* __restrict__ b_ih,
                            const float* __restrict__ b_hh) {
    int gid = blockIdx.x * blockDim.x + threadIdx.x;
    int stride = gridDim.x * blockDim.x;
    // W_ih: [j=4H][k=E] row-major -> g_Wih2[k*G4 + j] = {w,w}
    for (int i = gid; i < G4 * CHAR_EMB; i += stride) {
        int j = i / CHAR_EMB, k = i % CHAR_EMB;
        float w = W_ih[i];
        g_Wih2[k * G4 + j] = pack2(w, w);
    }
    // W_hh: [j=4H][k=H]
    for (int i = gid; i < G4 * CHAR_HID; i += stride) {
        int j = i >> 7, k = i & 127;
        float w = W_hh[i];
        g_Whh2[k * G4 + j] = pack2(w, w);
    }
    for (int i = gid; i < G4; i += stride)
        g_bsum[i] = b_ih[i] + b_hh[i];
}

// ---------------- glove partial sums ----------------
__global__ void glove_kernel(const int* __restrict__ wid,
                             const float* __restrict__ table) {
    __shared__ int idx[WPB];
    int tid = threadIdx.x;
    if (tid < WPB) idx[tid] = wid[blockIdx.x * WPB + tid];
    __syncthreads();
    if (tid < GLOVE_DIM) {
        float s = 0.0f;
        #pragma unroll 8
        for (int w = 0; w < WPB; w++)
            s += __ldg(table + (long)idx[w] * GLOVE_DIM + tid);
        g_Gpart[blockIdx.x * GLOVE_DIM + tid] = s;
    }
}

// ---------------- char LSTM: 32 words per block ----------------
// tid = grp*128 + n.  Thread owns hidden unit n for its group's 16 words
// (8 f32x2 word-pairs), computing all 4 gates via fma.rn.f32x2.
__global__ __launch_bounds__(256, 1)
void lstm_kernel(const int* __restrict__ char_idx,
                 const float* __restrict__ cemb) {
    extern __shared__ float sm[];
    float* xT   = sm;                                          // [t][k][w]  16*50*32
    float* hsh  = sm + WORD_LEN * CHAR_EMB * WPB;              // [k][HSTRIDE]
    float* ssum = hsh + CHAR_HID * HSTRIDE;                    // [256]

    const int tid = threadIdx.x;
    const int n   = tid & (CHAR_HID - 1);
    const int grp = tid >> 7;
    const int w0  = blockIdx.x * WPB;

    // zero h state (incl. padding)
    for (int i = tid; i < CHAR_HID * HSTRIDE; i += 256) hsh[i] = 0.0f;

    // gather all char embeddings, transposed to [t][k][w]
    for (int p = tid; p < WPB * WORD_LEN; p += 256) {
        int w = p & (WPB - 1);
        int t = p >> 5;
        int ci = char_idx[(w0 + w) * WORD_LEN + t];
        const float2* src = reinterpret_cast<const float2*>(cemb + ci * CHAR_EMB);
        float* dst = xT + (t * CHAR_EMB) * WPB + w;
        #pragma unroll
        for (int k2 = 0; k2 < CHAR_EMB / 2; k2++) {
            float2 v = __ldg(&src[k2]);
            dst[(2 * k2) * WPB]     = v.x;
            dst[(2 * k2 + 1) * WPB] = v.y;
        }
    }

    const ull bi = pack2(g_bsum[n],       g_bsum[n]);
    const ull bf = pack2(g_bsum[n + 128], g_bsum[n + 128]);
    const ull bg = pack2(g_bsum[n + 256], g_bsum[n + 256]);
    const ull bo = pack2(g_bsum[n + 384], g_bsum[n + 384]);

    float c[16];
    #pragma unroll
    for (int j = 0; j < 16; j++) c[j] = 0.0f;
    float hval[16];

    __syncthreads();

    for (int t = 0; t < WORD_LEN; t++) {
        ull acc[8][4];
        #pragma unroll
        for (int j = 0; j < 8; j++) {
            acc[j][0] = bi; acc[j][1] = bf; acc[j][2] = bg; acc[j][3] = bo;
        }

        // ---- x @ W_ih^T ----
        {
            const float* xbase = xT + (t * CHAR_EMB) * WPB + grp * 16;
            const ull* Wp = g_Wih2 + n;
            #pragma unroll 10
            for (int k = 0; k < CHAR_EMB; k++) {
                ull wi2 = __ldg(Wp + k * G4);
                ull wf2 = __ldg(Wp + k * G4 + 128);
                ull wg2 = __ldg(Wp + k * G4 + 256);
                ull wo2 = __ldg(Wp + k * G4 + 384);
                const ull* xp = reinterpret_cast<const ull*>(xbase + k * WPB);
                #pragma unroll
                for (int j = 0; j < 8; j++) {
                    ull x2 = xp[j];
                    ffma2(acc[j][0], wi2, x2);
                    ffma2(acc[j][1], wf2, x2);
                    ffma2(acc[j][2], wg2, x2);
                    ffma2(acc[j][3], wo2, x2);
                }
            }
        }
        // ---- h @ W_hh^T (h == 0 at t==0, skip) ----
        if (t) {
            const float* hbase = hsh + grp * 16;
            const ull* Wp = g_Whh2 + n;
            #pragma unroll 8
            for (int k = 0; k < CHAR_HID; k++) {
                ull wi2 = __ldg(Wp + k * G4);
                ull wf2 = __ldg(Wp + k * G4 + 128);
                ull wg2 = __ldg(Wp + k * G4 + 256);
                ull wo2 = __ldg(Wp + k * G4 + 384);
                const ull* hp = reinterpret_cast<const ull*>(hbase + k * HSTRIDE);
                #pragma unroll
                for (int j = 0; j < 8; j++) {
                    ull h2 = hp[j];
                    ffma2(acc[j][0], wi2, h2);
                    ffma2(acc[j][1], wf2, h2);
                    ffma2(acc[j][2], wg2, h2);
                    ffma2(acc[j][3], wo2, h2);
                }
            }
        }

        __syncthreads();   // all reads of hsh done before overwrite

        #pragma unroll
        for (int j = 0; j < 8; j++) {
            float iv0, iv1, fv0, fv1, gv0, gv1, ov0, ov1;
            unpack2(acc[j][0], iv0, iv1);
            unpack2(acc[j][1], fv0, fv1);
            unpack2(acc[j][2], gv0, gv1);
            unpack2(acc[j][3], ov0, ov1);
            {
                int w = 2 * j;
                float cc = sigmf(fv0) * c[w] + sigmf(iv0) * tanhf_(gv0);
                c[w] = cc;
                hval[w] = sigmf(ov0) * tanhf_(cc);
            }
            {
                int w = 2 * j + 1;
                float cc = sigmf(fv1) * c[w] + sigmf(iv1) * tanhf_(gv1);
                c[w] = cc;
                hval[w] = sigmf(ov1) * tanhf_(cc);
            }
        }

        if (t + 1 < WORD_LEN) {
            #pragma unroll
            for (int j = 0; j < 16; j++)
                hsh[n * HSTRIDE + grp * 16 + j] = hval[j];
        }
        __syncthreads();
    }

    // per-block partial sum of final h over the 32 words
    float s = 0.0f;
    #pragma unroll
    for (int j = 0; j < 16; j++) s += hval[j];
    ssum[tid] = s;
    __syncthreads();
    if (tid < CHAR_HID)
        g_Hpart[blockIdx.x * CHAR_HID + tid] = ssum[tid] + ssum[tid + 128];
}

// ---------------- avg: reduce the 128 block partials ----------------
__global__ void avg_kernel() {
    int tid = threadIdx.x;  // 512 threads, 1 block
    if (tid < GLOVE_DIM) {
        float s = 0.0f;
        #pragma unroll 8
        for (int b = 0; b < NBLK; b++) s += g_Gpart[b * GLOVE_DIM + tid];
        g_avg[tid] = s * (1.0f / N_WORDS);
    } else if (tid < FEAT) {
        int nn = tid - GLOVE_DIM;
        float s = 0.0f;
        #pragma unroll 8
        for (int b = 0; b < NBLK; b++) s += g_Hpart[b * CHAR_HID + nn];
        g_avg[tid] = s * (1.0f / N_WORDS);
    }
}

// ---------------- fc1 + relu: one warp per hidden unit ----------------
__global__ __launch_bounds__(256)
void fc1_kernel(const float* __restrict__ fc1_w,
                const float* __restrict__ fc1_b) {
    int warp = (blockIdx.x * blockDim.x + threadIdx.x) >> 5;  // 0..511
    int lane = threadIdx.x & 31;
    const float* wrow = fc1_w + warp * FEAT;
    float acc = 0.0f;
    #pragma unroll
    for (int d = lane; d < FEAT; d += 32)
        acc = fmaf(g_avg[d], __ldg(wrow + d), acc);
    #pragma unroll
    for (int off = 16; off > 0; off >>= 1)
        acc += __shfl_down_sync(0xFFFFFFFFu, acc, off);
    if (lane == 0)
        g_hid[warp] = fmaxf(acc + fc1_b[warp], 0.0f);
}

// ---------------- fc2 ----------------
__global__ void fc2_kernel(const float* __restrict__ fc2_w,
                           const float* __restrict__ fc2_b,
                           float* __restrict__ out) {
    __shared__ float red0[HIDDEN];
    __shared__ float red1[HIDDEN];
    int tid = threadIdx.x;  // 512 threads
    float h = g_hid[tid];
    red0[tid] = h * fc2_w[tid];
    red1[tid] = h * fc2_w[HIDDEN + tid];
    __syncthreads();
    for (int s = 256; s > 0; s >>= 1) {
        if (tid < s) {
            red0[tid] += red0[tid + s];
            red1[tid] += red1[tid + s];
        }
        __syncthreads();
    }
    if (tid == 0) {
        out[0] = red0[0] + fc2_b[0];
        out[1] = red1[0] + fc2_b[1];
    }
}

// ---------------- launch ----------------
extern "C" void kernel_launch(void* const* d_in, const int* in_sizes, int n_in,
                              void* d_out, int out_size) {
    const int*   word_idx = (const int*)  d_in[0];
    const int*   char_idx = (const int*)  d_in[1];
    const float* glove    = (const float*)d_in[2];
    const float* cemb     = (const float*)d_in[3];
    const float* W_ih     = (const float*)d_in[4];
    const float* W_hh     = (const float*)d_in[5];
    const float* b_ih     = (const float*)d_in[6];
    const float* b_hh     = (const float*)d_in[7];
    const float* fc1_w    = (const float*)d_in[8];
    const float* fc1_b    = (const float*)d_in[9];
    const float* fc2_w    = (const float*)d_in[10];
    const float* fc2_b    = (const float*)d_in[11];
    float* out = (float*)d_out;

    const int smem_bytes =
        (WORD_LEN * CHAR_EMB * WPB + CHAR_HID * HSTRIDE + 256) * (int)sizeof(float);
    cudaFuncSetAttribute(lstm_kernel,
                         cudaFuncAttributeMaxDynamicSharedMemorySize, smem_bytes);

    prep_kernel<<<128, 256>>>(W_ih, W_hh, b_ih, b_hh);
    glove_kernel<<<NBLK, 320>>>(word_idx, glove);
    lstm_kernel<<<NBLK, 256, smem_bytes>>>(char_idx, cemb);
    avg_kernel<<<1, 512>>>();
    fc1_kernel<<<64, 256>>>(fc1_w, fc1_b);
    fc2_kernel<<<1, 512>>>(fc2_w, fc2_b, out);
}

// round 9
// speedup vs baseline: 1.0966x; 1.0966x over previous
#include <cuda_runtime.h>
#include <cuda_bf16.h>

// ---------------- problem constants ----------------
#define N_WORDS   4096
#define WORD_LEN  16
#define GLOVE_DIM 300
#define CHAR_EMB  50
#define CHAR_HID  128
#define G4        512           // 4*CHAR_HID
#define HIDDEN    512
#define FEAT      428           // GLOVE_DIM + CHAR_HID
#define WPB       32            // words per block
#define NBLK      (N_WORDS / WPB)   // 128
#define HSTRIDE   34            // padded h row stride (floats)

typedef unsigned long long ull;

// ---------------- device scratch (static; no allocations allowed) ----------------
// weights: [k][p][n] as ulonglong2, p=0 -> {i,i,f,f}, p=1 -> {g,g,o,o}
__device__ ulonglong2 g_Wih4[CHAR_EMB * 2 * CHAR_HID];
__device__ ulonglong2 g_Whh4[CHAR_HID * 2 * CHAR_HID];
__device__ float g_bsum[G4];                // b_ih + b_hh
__device__ float g_Gpart[NBLK * GLOVE_DIM];
__device__ float g_Hpart[NBLK * CHAR_HID];
__device__ float g_avg[FEAT];
__device__ float g_hid[HIDDEN];

// ---------------- packed f32x2 helpers ----------------
static __device__ __forceinline__ ull pack2(float lo, float hi) {
    ull r;
    asm("mov.b64 %0, {%1, %2};" : "=l"(r) : "f"(lo), "f"(hi));
    return r;
}
static __device__ __forceinline__ void unpack2(ull v, float &lo, float &hi) {
    asm("mov.b64 {%0, %1}, %2;" : "=f"(lo), "=f"(hi) : "l"(v));
}
static __device__ __forceinline__ void ffma2(ull &d, ull a, ull b) {
    // d = a * b + d   (two independent fp32 FMAs per instruction)
    asm("fma.rn.f32x2 %0, %1, %2, %0;" : "+l"(d) : "l"(a), "l"(b));
}

static __device__ __forceinline__ float sigmf(float x) {
    return __fdividef(1.0f, 1.0f + __expf(-x));
}
static __device__ __forceinline__ float tanhf_(float x) {
    float e = __expf(2.0f * x);
    return __fdividef(e - 1.0f, e + 1.0f);
}

// ---------------- prep: transpose + duplicate weights, fold bias ----------------
__global__ void prep_kernel(const float* __restrict__ W_ih,
                            const float* __restrict__ W_hh,
                            const float* __restrict__ b_ih,
                            const float* __restrict__ b_hh) {
    int gid = blockIdx.x * blockDim.x + threadIdx.x;
    int stride = gridDim.x * blockDim.x;
    // W_ih: [j=4H][k=E] row-major.  gate = j>>7, n = j&127, p = gate>>1, slot = gate&1.
    for (int i = gid; i < G4 * CHAR_EMB; i += stride) {
        int j = i / CHAR_EMB, k = i % CHAR_EMB;
        int gate = j >> 7, n = j & 127;
        float w = W_ih[i];
        ull* dst = reinterpret_cast<ull*>(&g_Wih4[(k * 2 + (gate >> 1)) * CHAR_HID + n]);
        dst[gate & 1] = pack2(w, w);
    }
    // W_hh: [j=4H][k=H]
    for (int i = gid; i < G4 * CHAR_HID; i += stride) {
        int j = i >> 7, k = i & 127;
        int gate = j >> 7, n = j & 127;
        float w = W_hh[i];
        ull* dst = reinterpret_cast<ull*>(&g_Whh4[(k * 2 + (gate >> 1)) * CHAR_HID + n]);
        dst[gate & 1] = pack2(w, w);
    }
    for (int i = gid; i < G4; i += stride)
        g_bsum[i] = b_ih[i] + b_hh[i];
}

// ---------------- glove partial sums ----------------
__global__ void glove_kernel(const int* __restrict__ wid,
                             const float* __restrict__ table) {
    __shared__ int idx[WPB];
    int tid = threadIdx.x;
    if (tid < WPB) idx[tid] = wid[blockIdx.x * WPB + tid];
    __syncthreads();
    if (tid < GLOVE_DIM) {
        float s = 0.0f;
        #pragma unroll 8
        for (int w = 0; w < WPB; w++)
            s += __ldg(table + (long)idx[w] * GLOVE_DIM + tid);
        g_Gpart[blockIdx.x * GLOVE_DIM + tid] = s;
    }
}

// ---------------- char LSTM: 32 words per block, 512 threads ----------------
// tid = grp*128 + n, grp in 0..3.  Thread owns hidden unit n for its group's
// 8 words (4 f32x2 word-pairs), computing all 4 gates via fma.rn.f32x2.
__global__ __launch_bounds__(512, 1)
void lstm_kernel(const int* __restrict__ char_idx,
                 const float* __restrict__ cemb) {
    extern __shared__ float sm[];
    float* xT   = sm;                                          // [t][k][w]  16*50*32
    float* hsh  = sm + WORD_LEN * CHAR_EMB * WPB;              // [k][HSTRIDE]
    float* ssum = hsh + CHAR_HID * HSTRIDE;                    // [512]

    const int tid = threadIdx.x;
    const int n   = tid & (CHAR_HID - 1);
    const int grp = tid >> 7;                                  // 0..3
    const int w0  = blockIdx.x * WPB;

    // zero h state (incl. padding)
    for (int i = tid; i < CHAR_HID * HSTRIDE; i += 512) hsh[i] = 0.0f;

    // gather all char embeddings, transposed to [t][k][w] (one word-step per thread)
    {
        int p = tid;                 // 512 = WPB * WORD_LEN exactly
        int w = p & (WPB - 1);
        int t = p >> 5;
        int ci = char_idx[(w0 + w) * WORD_LEN + t];
        const float2* src = reinterpret_cast<const float2*>(cemb + ci * CHAR_EMB);
        float* dst = xT + (t * CHAR_EMB) * WPB + w;
        #pragma unroll
        for (int k2 = 0; k2 < CHAR_EMB / 2; k2++) {
            float2 v = __ldg(&src[k2]);
            dst[(2 * k2) * WPB]     = v.x;
            dst[(2 * k2 + 1) * WPB] = v.y;
        }
    }

    const ull bi = pack2(g_bsum[n],       g_bsum[n]);
    const ull bf = pack2(g_bsum[n + 128], g_bsum[n + 128]);
    const ull bg = pack2(g_bsum[n + 256], g_bsum[n + 256]);
    const ull bo = pack2(g_bsum[n + 384], g_bsum[n + 384]);

    float c[8];
    #pragma unroll
    for (int j = 0; j < 8; j++) c[j] = 0.0f;
    float hval[8];

    __syncthreads();

    for (int t = 0; t < WORD_LEN; t++) {
        ull acc[4][4];
        #pragma unroll
        for (int j = 0; j < 4; j++) {
            acc[j][0] = bi; acc[j][1] = bf; acc[j][2] = bg; acc[j][3] = bo;
        }

        // ---- x @ W_ih^T ----
        {
            const float* xbase = xT + (t * CHAR_EMB) * WPB + grp * 8;
            const ulonglong2* Wp = g_Wih4 + n;
            #pragma unroll 10
            for (int k = 0; k < CHAR_EMB; k++) {
                ulonglong2 wif = __ldg(Wp + (2 * k) * CHAR_HID);
                ulonglong2 wgo = __ldg(Wp + (2 * k + 1) * CHAR_HID);
                const ull* xp = reinterpret_cast<const ull*>(xbase + k * WPB);
                #pragma unroll
                for (int j = 0; j < 4; j++) {
                    ull x2 = xp[j];
                    ffma2(acc[j][0], wif.x, x2);
                    ffma2(acc[j][1], wif.y, x2);
                    ffma2(acc[j][2], wgo.x, x2);
                    ffma2(acc[j][3], wgo.y, x2);
                }
            }
        }
        // ---- h @ W_hh^T (h == 0 at t==0, skip) ----
        if (t) {
            const float* hbase = hsh + grp * 8;
            const ulonglong2* Wp = g_Whh4 + n;
            #pragma unroll 16
            for (int k = 0; k < CHAR_HID; k++) {
                ulonglong2 wif = __ldg(Wp + (2 * k) * CHAR_HID);
                ulonglong2 wgo = __ldg(Wp + (2 * k + 1) * CHAR_HID);
                const ull* hp = reinterpret_cast<const ull*>(hbase + k * HSTRIDE);
                #pragma unroll
                for (int j = 0; j < 4; j++) {
                    ull h2 = hp[j];
                    ffma2(acc[j][0], wif.x, h2);
                    ffma2(acc[j][1], wif.y, h2);
                    ffma2(acc[j][2], wgo.x, h2);
                    ffma2(acc[j][3], wgo.y, h2);
                }
            }
        }

        __syncthreads();   // all reads of hsh done before overwrite

        #pragma unroll
        for (int j = 0; j < 4; j++) {
            float iv0, iv1, fv0, fv1, gv0, gv1, ov0, ov1;
            unpack2(acc[j][0], iv0, iv1);
            unpack2(acc[j][1], fv0, fv1);
            unpack2(acc[j][2], gv0, gv1);
            unpack2(acc[j][3], ov0, ov1);
            {
                int w = 2 * j;
                float cc = sigmf(fv0) * c[w] + sigmf(iv0) * tanhf_(gv0);
                c[w] = cc;
                hval[w] = sigmf(ov0) * tanhf_(cc);
            }
            {
                int w = 2 * j + 1;
                float cc = sigmf(fv1) * c[w] + sigmf(iv1) * tanhf_(gv1);
                c[w] = cc;
                hval[w] = sigmf(ov1) * tanhf_(cc);
            }
        }

        if (t + 1 < WORD_LEN) {
            #pragma unroll
            for (int j = 0; j < 8; j++)
                hsh[n * HSTRIDE + grp * 8 + j] = hval[j];
        }
        __syncthreads();
    }

    // per-block partial sum of final h over the 32 words
    float s = 0.0f;
    #pragma unroll
    for (int j = 0; j < 8; j++) s += hval[j];
    ssum[tid] = s;
    __syncthreads();
    if (tid < CHAR_HID)
        g_Hpart[blockIdx.x * CHAR_HID + tid] =
            ssum[tid] + ssum[tid + 128] + ssum[tid + 256] + ssum[tid + 384];
}

// ---------------- avg: one warp per feature ----------------
__global__ __launch_bounds__(128)
void avg_kernel() {
    int f    = blockIdx.x * 4 + (threadIdx.x >> 5);   // 0..427  (107 blocks * 4 warps)
    int lane = threadIdx.x & 31;
    float s = 0.0f;
    if (f < GLOVE_DIM) {
        #pragma unroll
        for (int b = lane; b < NBLK; b += 32) s += g_Gpart[b * GLOVE_DIM + f];
    } else {
        int nn = f - GLOVE_DIM;
        #pragma unroll
        for (int b = lane; b < NBLK; b += 32) s += g_Hpart[b * CHAR_HID + nn];
    }
    #pragma unroll
    for (int off = 16; off > 0; off >>= 1)
        s += __shfl_down_sync(0xFFFFFFFFu, s, off);
    if (lane == 0)
        g_avg[f] = s * (1.0f / N_WORDS);
}

// ---------------- fc1 + relu: one warp per hidden unit ----------------
__global__ __launch_bounds__(256)
void fc1_kernel(const float* __restrict__ fc1_w,
                const float* __restrict__ fc1_b) {
    int warp = (blockIdx.x * blockDim.x + threadIdx.x) >> 5;  // 0..511
    int lane = threadIdx.x & 31;
    const float* wrow = fc1_w + warp * FEAT;
    float acc = 0.0f;
    #pragma unroll
    for (int d = lane; d < FEAT; d += 32)
        acc = fmaf(g_avg[d], __ldg(wrow + d), acc);
    #pragma unroll
    for (int off = 16; off > 0; off >>= 1)
        acc += __shfl_down_sync(0xFFFFFFFFu, acc, off);
    if (lane == 0)
        g_hid[warp] = fmaxf(acc + fc1_b[warp], 0.0f);
}

// ---------------- fc2 ----------------
__global__ void fc2_kernel(const float* __restrict__ fc2_w,
                           const float* __restrict__ fc2_b,
                           float* __restrict__ out) {
    __shared__ float red0[HIDDEN];
    __shared__ float red1[HIDDEN];
    int tid = threadIdx.x;  // 512 threads
    float h = g_hid[tid];
    red0[tid] = h * fc2_w[tid];
    red1[tid] = h * fc2_w[HIDDEN + tid];
    __syncthreads();
    for (int s = 256; s > 0; s >>= 1) {
        if (tid < s) {
            red0[tid] += red0[tid + s];
            red1[tid] += red1[tid + s];
        }
        __syncthreads();
    }
    if (tid == 0) {
        out[0] = red0[0] + fc2_b[0];
        out[1] = red1[0] + fc2_b[1];
    }
}

// ---------------- launch ----------------
extern "C" void kernel_launch(void* const* d_in, const int* in_sizes, int n_in,
                              void* d_out, int out_size) {
    const int*   word_idx = (const int*)  d_in[0];
    const int*   char_idx = (const int*)  d_in[1];
    const float* glove    = (const float*)d_in[2];
    const float* cemb     = (const float*)d_in[3];
    const float* W_ih     = (const float*)d_in[4];
    const float* W_hh     = (const float*)d_in[5];
    const float* b_ih     = (const float*)d_in[6];
    const float* b_hh     = (const float*)d_in[7];
    const float* fc1_w    = (const float*)d_in[8];
    const float* fc1_b    = (const float*)d_in[9];
    const float* fc2_w    = (const float*)d_in[10];
    const float* fc2_b    = (const float*)d_in[11];
    float* out = (float*)d_out;

    const int smem_bytes =
        (WORD_LEN * CHAR_EMB * WPB + CHAR_HID * HSTRIDE + 512) * (int)sizeof(float);
    cudaFuncSetAttribute(lstm_kernel,
                         cudaFuncAttributeMaxDynamicSharedMemorySize, smem_bytes);

    prep_kernel<<<128, 256>>>(W_ih, W_hh, b_ih, b_hh);
    glove_kernel<<<NBLK, 320>>>(word_idx, glove);
    lstm_kernel<<<NBLK, 512, smem_bytes>>>(char_idx, cemb);
    avg_kernel<<<107, 128>>>();
    fc1_kernel<<<64, 256>>>(fc1_w, fc1_b);
    fc2_kernel<<<1, 512>>>(fc2_w, fc2_b, out);
}

// round 10
// speedup vs baseline: 1.0986x; 1.0019x over previous
#include <cuda_runtime.h>
#include <cuda_bf16.h>

// ---------------- problem constants ----------------
#define N_WORDS   4096
#define WORD_LEN  16
#define GLOVE_DIM 300
#define CHAR_EMB  50
#define CHAR_HID  128
#define G4        512           // 4*CHAR_HID
#define HIDDEN    512
#define FEAT      428           // GLOVE_DIM + CHAR_HID
#define WPB       32            // words per block
#define NBLK      (N_WORDS / WPB)   // 128
#define HSTRIDE   34            // padded h row stride (floats)

typedef unsigned long long ull;

// ---------------- device scratch (static; no allocations allowed) ----------------
// weights: [k][p][n] as ulonglong2, p=0 -> {i,i,f,f}, p=1 -> {g,g,o,o}
__device__ ulonglong2 g_Wih4[CHAR_EMB * 2 * CHAR_HID];
__device__ ulonglong2 g_Whh4[CHAR_HID * 2 * CHAR_HID];
__device__ float g_bsum[G4];                // b_ih + b_hh
__device__ float g_Gpart[NBLK * GLOVE_DIM];
__device__ float g_Hpart[NBLK * CHAR_HID];
__device__ float g_avg[FEAT];
__device__ float g_hid[HIDDEN];

// ---------------- packed f32x2 helpers ----------------
static __device__ __forceinline__ ull pack2(float lo, float hi) {
    ull r;
    asm("mov.b64 %0, {%1, %2};" : "=l"(r) : "f"(lo), "f"(hi));
    return r;
}
static __device__ __forceinline__ void unpack2(ull v, float &lo, float &hi) {
    asm("mov.b64 {%0, %1}, %2;" : "=f"(lo), "=f"(hi) : "l"(v));
}
static __device__ __forceinline__ void ffma2(ull &d, ull a, ull b) {
    // d = a * b + d   (two independent fp32 FMAs per instruction)
    asm("fma.rn.f32x2 %0, %1, %2, %0;" : "+l"(d) : "l"(a), "l"(b));
}

static __device__ __forceinline__ float sigmf(float x) {
    return __fdividef(1.0f, 1.0f + __expf(-x));
}
static __device__ __forceinline__ float tanhf_(float x) {
    float e = __expf(2.0f * x);
    return __fdividef(e - 1.0f, e + 1.0f);
}

// ---------------- prep: transpose + duplicate weights, fold bias ----------------
__global__ void prep_kernel(const float* __restrict__ W_ih,
                            const float* __restrict__ W_hh,
                            const float* __restrict__ b_ih,
                            const float* __restrict__ b_hh) {
    int gid = blockIdx.x * blockDim.x + threadIdx.x;
    int stride = gridDim.x * blockDim.x;
    // W_ih: [j=4H][k=E] row-major.  gate = j>>7, n = j&127, p = gate>>1, slot = gate&1.
    for (int i = gid; i < G4 * CHAR_EMB; i += stride) {
        int j = i / CHAR_EMB, k = i % CHAR_EMB;
        int gate = j >> 7, n = j & 127;
        float w = W_ih[i];
        ull* dst = reinterpret_cast<ull*>(&g_Wih4[(k * 2 + (gate >> 1)) * CHAR_HID + n]);
        dst[gate & 1] = pack2(w, w);
    }
    // W_hh: [j=4H][k=H]
    for (int i = gid; i < G4 * CHAR_HID; i += stride) {
        int j = i >> 7, k = i & 127;
        int gate = j >> 7, n = j & 127;
        float w = W_hh[i];
        ull* dst = reinterpret_cast<ull*>(&g_Whh4[(k * 2 + (gate >> 1)) * CHAR_HID + n]);
        dst[gate & 1] = pack2(w, w);
    }
    for (int i = gid; i < G4; i += stride)
        g_bsum[i] = b_ih[i] + b_hh[i];
}

// ---------------- glove partial sums ----------------
__global__ void glove_kernel(const int* __restrict__ wid,
                             const float* __restrict__ table) {
    __shared__ int idx[WPB];
    int tid = threadIdx.x;
    if (tid < WPB) idx[tid] = wid[blockIdx.x * WPB + tid];
    __syncthreads();
    if (tid < GLOVE_DIM) {
        float s = 0.0f;
        #pragma unroll 8
        for (int w = 0; w < WPB; w++)
            s += __ldg(table + (long)idx[w] * GLOVE_DIM + tid);
        g_Gpart[blockIdx.x * GLOVE_DIM + tid] = s;
    }
}

// ---------------- char LSTM: 32 words per block, 512 threads ----------------
// tid = grp*128 + n, grp in 0..3.  Thread owns hidden unit n for its group's
// 8 words (4 f32x2 word-pairs), computing all 4 gates via fma.rn.f32x2.
__global__ __launch_bounds__(512, 1)
void lstm_kernel(const int* __restrict__ char_idx,
                 const float* __restrict__ cemb) {
    extern __shared__ float sm[];
    float* xT   = sm;                                          // [t][k][w]  16*50*32
    float* hsh  = sm + WORD_LEN * CHAR_EMB * WPB;              // [k][HSTRIDE]
    float* ssum = hsh + CHAR_HID * HSTRIDE;                    // [512]

    const int tid = threadIdx.x;
    const int n   = tid & (CHAR_HID - 1);
    const int grp = tid >> 7;                                  // 0..3
    const int w0  = blockIdx.x * WPB;

    // zero h state (incl. padding)
    for (int i = tid; i < CHAR_HID * HSTRIDE; i += 512) hsh[i] = 0.0f;

    // gather all char embeddings, transposed to [t][k][w] (one word-step per thread)
    {
        int p = tid;                 // 512 = WPB * WORD_LEN exactly
        int w = p & (WPB - 1);
        int t = p >> 5;
        int ci = char_idx[(w0 + w) * WORD_LEN + t];
        const float2* src = reinterpret_cast<const float2*>(cemb + ci * CHAR_EMB);
        float* dst = xT + (t * CHAR_EMB) * WPB + w;
        #pragma unroll
        for (int k2 = 0; k2 < CHAR_EMB / 2; k2++) {
            float2 v = __ldg(&src[k2]);
            dst[(2 * k2) * WPB]     = v.x;
            dst[(2 * k2 + 1) * WPB] = v.y;
        }
    }

    const ull bi = pack2(g_bsum[n],       g_bsum[n]);
    const ull bf = pack2(g_bsum[n + 128], g_bsum[n + 128]);
    const ull bg = pack2(g_bsum[n + 256], g_bsum[n + 256]);
    const ull bo = pack2(g_bsum[n + 384], g_bsum[n + 384]);

    float c[8];
    #pragma unroll
    for (int j = 0; j < 8; j++) c[j] = 0.0f;
    float hval[8];

    __syncthreads();

    for (int t = 0; t < WORD_LEN; t++) {
        ull acc[4][4];
        #pragma unroll
        for (int j = 0; j < 4; j++) {
            acc[j][0] = bi; acc[j][1] = bf; acc[j][2] = bg; acc[j][3] = bo;
        }

        // ---- x @ W_ih^T ----
        {
            const float* xbase = xT + (t * CHAR_EMB) * WPB + grp * 8;
            const ulonglong2* Wp = g_Wih4 + n;
            #pragma unroll 10
            for (int k = 0; k < CHAR_EMB; k++) {
                ulonglong2 wif = __ldg(Wp + (2 * k) * CHAR_HID);
                ulonglong2 wgo = __ldg(Wp + (2 * k + 1) * CHAR_HID);
                const ull* xp = reinterpret_cast<const ull*>(xbase + k * WPB);
                #pragma unroll
                for (int j = 0; j < 4; j++) {
                    ull x2 = xp[j];
                    ffma2(acc[j][0], wif.x, x2);
                    ffma2(acc[j][1], wif.y, x2);
                    ffma2(acc[j][2], wgo.x, x2);
                    ffma2(acc[j][3], wgo.y, x2);
                }
            }
        }
        // ---- h @ W_hh^T (h == 0 at t==0, skip) ----
        if (t) {
            const float* hbase = hsh + grp * 8;
            const ulonglong2* Wp = g_Whh4 + n;
            #pragma unroll 16
            for (int k = 0; k < CHAR_HID; k++) {
                ulonglong2 wif = __ldg(Wp + (2 * k) * CHAR_HID);
                ulonglong2 wgo = __ldg(Wp + (2 * k + 1) * CHAR_HID);
                const ull* hp = reinterpret_cast<const ull*>(hbase + k * HSTRIDE);
                #pragma unroll
                for (int j = 0; j < 4; j++) {
                    ull h2 = hp[j];
                    ffma2(acc[j][0], wif.x, h2);
                    ffma2(acc[j][1], wif.y, h2);
                    ffma2(acc[j][2], wgo.x, h2);
                    ffma2(acc[j][3], wgo.y, h2);
                }
            }
        }

        __syncthreads();   // all reads of hsh done before overwrite

        #pragma unroll
        for (int j = 0; j < 4; j++) {
            float iv0, iv1, fv0, fv1, gv0, gv1, ov0, ov1;
            unpack2(acc[j][0], iv0, iv1);
            unpack2(acc[j][1], fv0, fv1);
            unpack2(acc[j][2], gv0, gv1);
            unpack2(acc[j][3], ov0, ov1);
            {
                int w = 2 * j;
                float cc = sigmf(fv0) * c[w] + sigmf(iv0) * tanhf_(gv0);
                c[w] = cc;
                hval[w] = sigmf(ov0) * tanhf_(cc);
            }
            {
                int w = 2 * j + 1;
                float cc = sigmf(fv1) * c[w] + sigmf(iv1) * tanhf_(gv1);
                c[w] = cc;
                hval[w] = sigmf(ov1) * tanhf_(cc);
            }
        }

        if (t + 1 < WORD_LEN) {
            #pragma unroll
            for (int j = 0; j < 8; j++)
                hsh[n * HSTRIDE + grp * 8 + j] = hval[j];
        }
        __syncthreads();
    }

    // per-block partial sum of final h over the 32 words
    float s = 0.0f;
    #pragma unroll
    for (int j = 0; j < 8; j++) s += hval[j];
    ssum[tid] = s;
    __syncthreads();
    if (tid < CHAR_HID)
        g_Hpart[blockIdx.x * CHAR_HID + tid] =
            ssum[tid] + ssum[tid + 128] + ssum[tid + 256] + ssum[tid + 384];
}

// ---------------- avg: one warp per feature ----------------
__global__ __launch_bounds__(128)
void avg_kernel() {
    int f    = blockIdx.x * 4 + (threadIdx.x >> 5);   // 0..427  (107 blocks * 4 warps)
    int lane = threadIdx.x & 31;
    float s = 0.0f;
    if (f < GLOVE_DIM) {
        #pragma unroll
        for (int b = lane; b < NBLK; b += 32) s += g_Gpart[b * GLOVE_DIM + f];
    } else {
        int nn = f - GLOVE_DIM;
        #pragma unroll
        for (int b = lane; b < NBLK; b += 32) s += g_Hpart[b * CHAR_HID + nn];
    }
    #pragma unroll
    for (int off = 16; off > 0; off >>= 1)
        s += __shfl_down_sync(0xFFFFFFFFu, s, off);
    if (lane == 0)
        g_avg[f] = s * (1.0f / N_WORDS);
}

// ---------------- fc1 + relu: one warp per hidden unit ----------------
__global__ __launch_bounds__(256)
void fc1_kernel(const float* __restrict__ fc1_w,
                const float* __restrict__ fc1_b) {
    int warp = (blockIdx.x * blockDim.x + threadIdx.x) >> 5;  // 0..511
    int lane = threadIdx.x & 31;
    const float* wrow = fc1_w + warp * FEAT;
    float acc = 0.0f;
    #pragma unroll
    for (int d = lane; d < FEAT; d += 32)
        acc = fmaf(g_avg[d], __ldg(wrow + d), acc);
    #pragma unroll
    for (int off = 16; off > 0; off >>= 1)
        acc += __shfl_down_sync(0xFFFFFFFFu, acc, off);
    if (lane == 0)
        g_hid[warp] = fmaxf(acc + fc1_b[warp], 0.0f);
}

// ---------------- fc2 ----------------
__global__ void fc2_kernel(const float* __restrict__ fc2_w,
                           const float* __restrict__ fc2_b,
                           float* __restrict__ out) {
    __shared__ float red0[HIDDEN];
    __shared__ float red1[HIDDEN];
    int tid = threadIdx.x;  // 512 threads
    float h = g_hid[tid];
    red0[tid] = h * fc2_w[tid];
    red1[tid] = h * fc2_w[HIDDEN + tid];
    __syncthreads();
    for (int s = 256; s > 0; s >>= 1) {
        if (tid < s) {
            red0[tid] += red0[tid + s];
            red1[tid] += red1[tid + s];
        }
        __syncthreads();
    }
    if (tid == 0) {
        out[0] = red0[0] + fc2_b[0];
        out[1] = red1[0] + fc2_b[1];
    }
}

// ---------------- launch ----------------
extern "C" void kernel_launch(void* const* d_in, const int* in_sizes, int n_in,
                              void* d_out, int out_size) {
    const int*   word_idx = (const int*)  d_in[0];
    const int*   char_idx = (const int*)  d_in[1];
    const float* glove    = (const float*)d_in[2];
    const float* cemb     = (const float*)d_in[3];
    const float* W_ih     = (const float*)d_in[4];
    const float* W_hh     = (const float*)d_in[5];
    const float* b_ih     = (const float*)d_in[6];
    const float* b_hh     = (const float*)d_in[7];
    const float* fc1_w    = (const float*)d_in[8];
    const float* fc1_b    = (const float*)d_in[9];
    const float* fc2_w    = (const float*)d_in[10];
    const float* fc2_b    = (const float*)d_in[11];
    float* out = (float*)d_out;

    const int smem_bytes =
        (WORD_LEN * CHAR_EMB * WPB + CHAR_HID * HSTRIDE + 512) * (int)sizeof(float);
    cudaFuncSetAttribute(lstm_kernel,
                         cudaFuncAttributeMaxDynamicSharedMemorySize, smem_bytes);

    prep_kernel<<<128, 256>>>(W_ih, W_hh, b_ih, b_hh);
    glove_kernel<<<NBLK, 320>>>(word_idx, glove);
    lstm_kernel<<<NBLK, 512, smem_bytes>>>(char_idx, cemb);
    avg_kernel<<<107, 128>>>();
    fc1_kernel<<<64, 256>>>(fc1_w, fc1_b);
    fc2_kernel<<<1, 512>>>(fc2_w, fc2_b, out);
}